// round 14
// baseline (speedup 1.0000x reference)
#include <cuda_runtime.h>
#include <cuda_fp16.h>
#include <cstdint>
#include <cstddef>

#define HDIM   512
#define KDIM   1024
#define DPAIR  256
#define NTOK   128
#define OUTC   774
#define UVSTRIDE 6144
#define NCH    32            // pair: 1024 / 32
#define NCHUV  16            // uv:   512 / 32

// device scratch (no allocs allowed)
__device__ float    g_UV[(size_t)4 * NTOK * UVSTRIDE];    // u/v activations, plain k order
__device__ uint32_t g_W2B[(size_t)3 * NCH * DPAIR * 16];  // W2 fp16 [m][c][n][qpos][kb][p]
__device__ uint32_t g_W1B[(size_t)NCHUV * UVSTRIDE * 16]; // W1 fp16 [c][n_glob][qpos][kb][p]
__device__ uint32_t g_PH [(size_t)8 * NCHUV * 1024];      // P fp16 frag chunks [blk][c][4KB]

// ---------------- pair_mma smem layout (bytes), per CTA (3 CTAs/SM) --------
#define ZS_OFF(s) ((s) * 4096)            // 2 x 4KB  -> 8192
#define BS_OFF(s) (8192 + (s) * 16384)    // 2 x 16KB -> 40960
#define W3_OFF    40960                   // 2048
#define LOG_OFF   43008                   // 2048
#define SMEM_TOTAL 45056                  // x3 CTAs = 135168 <= 228KB

// ---------------- uv_mma smem layout: 2 stages of A(4KB)+B(16KB) ----------
#define AS_UV(s)  ((s) * 20480)
#define BS_UV(s)  ((s) * 20480 + 4096)
#define SMEM_UV   40960

// ---------------- helpers ----------------
__device__ __forceinline__ uint32_t smem_u32(const void* p) {
    uint32_t a;
    asm("{ .reg .u64 t; cvta.to.shared.u64 t, %1; cvt.u32.u64 %0, t; }"
        : "=r"(a) : "l"(p));
    return a;
}
__device__ __forceinline__ void cp16(uint32_t dst, const void* src) {
    asm volatile("cp.async.cg.shared.global [%0], [%1], 16;"
                 :: "r"(dst), "l"(src));
}
__device__ __forceinline__ void cp_commit() {
    asm volatile("cp.async.commit_group;" ::: "memory");
}
__device__ __forceinline__ void cp_wait0() {
    asm volatile("cp.async.wait_group 0;" ::: "memory");
}
__device__ __forceinline__ float2 add2(float2 a, float2 b) { // packed fp32x2 add
    float2 d;
    asm("add.rn.f32x2 %0, %1, %2;"
        : "=l"(*reinterpret_cast<unsigned long long*>(&d))
        : "l"(*reinterpret_cast<const unsigned long long*>(&a)),
          "l"(*reinterpret_cast<const unsigned long long*>(&b)));
    return d;
}
// relu + round-to-nearest fp16 pair: {lo=max(z.x,0), hi=max(z.y,0)}
__device__ __forceinline__ uint32_t cvt_relu_h2(float2 z) {
    uint32_t d;
    asm("cvt.rn.relu.f16x2.f32 %0, %1, %2;" : "=r"(d) : "f"(z.y), "f"(z.x));
    return d;
}
__device__ __forceinline__ uint32_t pack_h2(float lo, float hi) {
    __half2 hh = __halves2half2(__float2half_rn(lo), __float2half_rn(hi));
    return *reinterpret_cast<uint32_t*>(&hh);
}
__device__ __forceinline__ void mma_f16(float* c, const uint32_t* a,
                                        uint32_t b0, uint32_t b1) {
    asm volatile(
        "mma.sync.aligned.m16n8k16.row.col.f32.f16.f16.f32 "
        "{%0,%1,%2,%3}, {%4,%5,%6,%7}, {%8,%9}, {%0,%1,%2,%3};"
        : "+f"(c[0]), "+f"(c[1]), "+f"(c[2]), "+f"(c[3])
        : "r"(a[0]), "r"(a[1]), "r"(a[2]), "r"(a[3]), "r"(b0), "r"(b1));
}

// ---------------------------------------------------------------------------
// Kernel A: packs. z=0: W2 (96 blocks); z=1: W1 (384 blocks); z=2: P (128).
// ---------------------------------------------------------------------------
__global__ __launch_bounds__(256, 2) void pack_all(
    const float* __restrict__ P,
    const float* __restrict__ W1_0,
    const float* __restrict__ W1_1,
    const float* __restrict__ W1_2,
    const float* __restrict__ W2_0,
    const float* __restrict__ W2_1,
    const float* __restrict__ W2_2)
{
    const int bx = blockIdx.x, tid = threadIdx.x;

    if (blockIdx.z == 0) {
        if (bx >= 96) return;
        const int m = bx >> 5, c = bx & 31;
        const float* W2 = (m == 0) ? W2_0 : ((m == 1) ? W2_1 : W2_2);
        const int n = tid;
        uint32_t* dst = g_W2B + (((size_t)m * NCH + c) * DPAIR + n) * 16;
        #pragma unroll
        for (int qpos = 0; qpos < 4; qpos++)
            #pragma unroll
            for (int kb = 0; kb < 2; kb++)
                #pragma unroll
                for (int p = 0; p < 2; p++) {
                    int k = c * 32 + kb * 16 + qpos * 2 + p * 8;
                    dst[qpos * 4 + kb * 2 + p] =
                        pack_h2(W2[(size_t)k * DPAIR + n],
                                W2[(size_t)(k + 1) * DPAIR + n]);
                }
        return;
    }

    if (blockIdx.z == 1) {
        // W1 pack: B[k][n_glob] -> [c][n_glob][qpos][kb][p]; K=512.
        const int c = bx / 24, nblk = bx % 24;
        const int n = nblk * 256 + tid;
        const int m = n >> 11, half = (n >> 10) & 1, ncol = n & 1023;
        const float* W1 = (m == 0) ? W1_0 : ((m == 1) ? W1_1 : W1_2);
        const float* src = W1 + (size_t)(half * 512) * 1024 + ncol;
        uint32_t* dst = g_W1B + ((size_t)c * UVSTRIDE + n) * 16;
        #pragma unroll
        for (int qpos = 0; qpos < 4; qpos++)
            #pragma unroll
            for (int kb = 0; kb < 2; kb++)
                #pragma unroll
                for (int p = 0; p < 2; p++) {
                    int k = c * 32 + kb * 16 + qpos * 2 + p * 8;
                    dst[qpos * 4 + kb * 2 + p] =
                        pack_h2(src[(size_t)k * 1024], src[(size_t)(k + 1) * 1024]);
                }
        return;
    }

    // z == 2: P pack into Z-fragment chunk layout. 128 blocks = blk(8) x c(16).
    if (bx >= 128) return;
    {
        const int blk = bx >> 4, c = bx & 15;
        const int kb = tid >> 7, rp = (tid >> 2) & 31, e = tid & 3;
        const int hh = ((e >> 1) ^ ((rp >> 1) & 1));
        const int k = c * 32 + kb * 16 + (e & 1) * 4 + hh * 8;
        const int r0 = blk * 64 + (rp >> 3) * 16 + (rp & 7);
        float4 p0 = *(const float4*)(P + (size_t)r0 * HDIM + k);
        float4 p1 = *(const float4*)(P + (size_t)(r0 + 8) * HDIM + k);
        uint4 zo;
        zo.x = pack_h2(p0.x, p0.y);
        zo.y = pack_h2(p1.x, p1.y);
        zo.z = pack_h2(p0.z, p0.w);
        zo.w = pack_h2(p1.z, p1.w);
        uint32_t* dst = g_PH + ((size_t)(blk * NCHUV + c)) * 1024;
        *(uint4*)((char*)dst + kb * 2048 + rp * 64 + e * 16) = zo;
    }
}

// ---------------------------------------------------------------------------
// Kernel B: uv GEMM on HMMA fp16. C[512,6144] = P @ W1cat, K=512. (R13 keeper)
// ---------------------------------------------------------------------------
__global__ __launch_bounds__(128, 2) void uv_mma(float* __restrict__ dummy)
{
    extern __shared__ char sm[];
    const uint32_t sb = smem_u32(sm);
    const int tid = threadIdx.x;
    const int l = tid & 31;
    const int qid = l >> 2, qpos = l & 3;
    const int wn = tid >> 5;             // 0..3

    const int cbk = blockIdx.x;          // 24 col blocks of 256
    const int blk = blockIdx.y;          // 8 row blocks of 64
    const int cb = cbk * 256;
    const int rb = blk * 64;

    const char* Abase = (const char*)(g_PH + (size_t)blk * NCHUV * 1024);
    const char* Bbase = (const char*)(g_W1B + ((size_t)0 * UVSTRIDE + cb) * 16);

    {
        cp16(sb + AS_UV(0) + (tid * 2) * 16,     Abase + (size_t)(tid * 2) * 16);
        cp16(sb + AS_UV(0) + (tid * 2 + 1) * 16, Abase + (size_t)(tid * 2 + 1) * 16);
        #pragma unroll
        for (int q = 0; q < 8; q++) {
            int fi = q * 128 + tid;
            cp16(sb + BS_UV(0) + fi * 16, Bbase + (size_t)fi * 16);
        }
        cp_commit();
    }

    float acc[4][8][4];
    #pragma unroll
    for (int mf = 0; mf < 4; mf++)
        #pragma unroll
        for (int nt = 0; nt < 8; nt++)
            #pragma unroll
            for (int cc = 0; cc < 4; cc++) acc[mf][nt][cc] = 0.f;

    const int sl0 = qpos + 4 * ((qid >> 1) & 1);
    const int sl1 = sl0 ^ 4;
    const uint32_t b_off = (uint32_t)(wn * 64 + qid) * 64 + qpos * 16;

    for (int c = 0; c < NCHUV; c++) {
        const int s = c & 1;
        cp_wait0();
        __syncthreads();

        if (c + 1 < NCHUV) {
            const char* ap = Abase + (size_t)(c + 1) * 4096;
            const char* wp = (const char*)(g_W1B + ((size_t)(c + 1) * UVSTRIDE + cb) * 16);
            cp16(sb + AS_UV(s ^ 1) + (tid * 2) * 16,     ap + (size_t)(tid * 2) * 16);
            cp16(sb + AS_UV(s ^ 1) + (tid * 2 + 1) * 16, ap + (size_t)(tid * 2 + 1) * 16);
            #pragma unroll
            for (int q = 0; q < 8; q++) {
                int fi = q * 128 + tid;
                cp16(sb + BS_UV(s ^ 1) + fi * 16, wp + (size_t)fi * 16);
            }
            cp_commit();
        }

        uint32_t a[2][4][4];
        #pragma unroll
        for (int kb = 0; kb < 2; kb++)
            #pragma unroll
            for (int mf = 0; mf < 4; mf++) {
                const uint32_t base = (uint32_t)AS_UV(s) + kb * 2048
                                    + (uint32_t)(mf * 8 + qid) * 64;
                uint2 lo = *(const uint2*)(sm + base + sl0 * 8);
                uint2 hi = *(const uint2*)(sm + base + sl1 * 8);
                a[kb][mf][0] = lo.x; a[kb][mf][1] = lo.y;
                a[kb][mf][2] = hi.x; a[kb][mf][3] = hi.y;
            }

        #pragma unroll
        for (int nt = 0; nt < 8; nt++) {
            uint4 bv = *(const uint4*)(sm + BS_UV(s) + b_off + nt * 512);
            #pragma unroll
            for (int mf = 0; mf < 4; mf++)
                mma_f16(acc[mf][nt], a[0][mf], bv.x, bv.y);
            #pragma unroll
            for (int mf = 0; mf < 4; mf++)
                mma_f16(acc[mf][nt], a[1][mf], bv.z, bv.w);
        }
    }

    #pragma unroll
    for (int mf = 0; mf < 4; mf++) {
        #pragma unroll
        for (int half = 0; half < 2; half++) {
            const int r = rb + mf * 16 + half * 8 + qid;
            float* orow = g_UV + (size_t)r * UVSTRIDE + cb + wn * 64;
            #pragma unroll
            for (int nt = 0; nt < 8; nt++) {
                *(float2*)(orow + nt * 8 + qpos * 2) =
                    make_float2(acc[mf][nt][half * 2], acc[mf][nt][half * 2 + 1]);
            }
        }
    }
    (void)dummy;
}

// ---------------------------------------------------------------------------
// Kernel C: fp16 HMMA pair MLP. 128 threads, 4 warps, 3 CTAs/SM.
// z-build reads u/v straight from g_UV via LDG (L1/L2-cached, no residency);
// kb-split A-fragment passes keep regs <= 170 so 3 CTAs fit the RF.
// ---------------------------------------------------------------------------
__global__ __launch_bounds__(128, 3) void pair_mma(
    const float* __restrict__ w3_0, const float* __restrict__ w3_1,
    const float* __restrict__ w3_2, float* __restrict__ out)
{
    extern __shared__ char sm[];
    const uint32_t sb = smem_u32(sm);
    const int tid = threadIdx.x;
    const int l = tid & 31;
    const int qid = l >> 2, qpos = l & 3;
    const int wn = tid >> 5;       // 0..3

    const int jt = blockIdx.x;     // 16 -> 8 j rows
    const int it = blockIdx.y;     // 16 -> 8 i rows
    const int bz = blockIdx.z;     // 12
    const int b = bz / 3, m = bz % 3;

    const float* w3 = (m == 0) ? w3_0 : ((m == 1) ? w3_1 : w3_2);
    ((float4*)(sm + W3_OFF))[tid] = ((const float4*)w3)[tid];

    const char* W2base = (const char*)(g_W2B + (size_t)m * NCH * DPAIR * 16);

    // ---- z-build constants: LDG sources in g_UV ----
    const int z_rp  = tid >> 2;                 // 0..31
    const int z_e   = tid & 3;
    const int z_blk = z_rp >> 3, z_qd = z_rp & 7;
    const int z_hh  = ((z_e >> 1) ^ ((z_rp >> 1) & 1));
    const int z_koff = (z_e & 1) * 4 + z_hh * 8;          // words; kb adds +16
    const float* uP = g_UV + (size_t)(b * NTOK + it * 8 + z_blk * 2) * UVSTRIDE
                    + m * 2048 + z_koff;
    const float* vP = g_UV + (size_t)(b * NTOK + jt * 8 + z_qd) * UVSTRIDE
                    + m * 2048 + 1024 + z_koff;
    const uint32_t z_dst = z_rp * 64 + z_e * 16;          // kb adds +2048 bytes

    // ---- prologue: B chunk 0 ----
    #pragma unroll
    for (int q = 0; q < 8; q++) {
        int fi = q * 128 + tid;
        cp16(sb + BS_OFF(0) + fi * 16, W2base + (size_t)fi * 16);
    }
    cp_commit();

    float acc[4][8][4];
    #pragma unroll
    for (int mf = 0; mf < 4; mf++)
        #pragma unroll
        for (int nt = 0; nt < 8; nt++)
            #pragma unroll
            for (int cc = 0; cc < 4; cc++) acc[mf][nt][cc] = 0.f;

    // A slots: h=0/1 -> slot = qpos + 4*(h ^ ((qid>>1)&1))
    const int sl0 = qpos + 4 * ((qid >> 1) & 1);
    const int sl1 = sl0 ^ 4;
    const uint32_t b_off = (uint32_t)(wn * 64 + qid) * 64 + qpos * 16;

    for (int c = 0; c < NCH; c++) {
        const int s = c & 1;

        // ---- z-build into zs[s]: u/v via LDG (L1-resident, broadcast-heavy) ----
        {
            const int ko = c * 32;
            #pragma unroll
            for (int kb = 0; kb < 2; kb++) {
                float4 u0 = *(const float4*)(uP + ko + kb * 16);
                float4 u1 = *(const float4*)(uP + UVSTRIDE + ko + kb * 16);
                float4 vv = *(const float4*)(vP + ko + kb * 16);
                uint4 zo;
                zo.x = cvt_relu_h2(add2(make_float2(u0.x, u0.y), make_float2(vv.x, vv.y)));
                zo.y = cvt_relu_h2(add2(make_float2(u1.x, u1.y), make_float2(vv.x, vv.y)));
                zo.z = cvt_relu_h2(add2(make_float2(u0.z, u0.w), make_float2(vv.z, vv.w)));
                zo.w = cvt_relu_h2(add2(make_float2(u1.z, u1.w), make_float2(vv.z, vv.w)));
                *(uint4*)(sm + ZS_OFF(s) + z_dst + kb * 2048) = zo;
            }
        }
        cp_wait0();              // B(c) arrived
        __syncthreads();         // z(c)+B(c) visible

        if (c + 1 < NCH) {       // stream B(c+1) into bs[s^1]
            const char* wp = W2base + (size_t)(c + 1) * 16384;
            #pragma unroll
            for (int q = 0; q < 8; q++) {
                int fi = q * 128 + tid;
                cp16(sb + BS_OFF(s ^ 1) + fi * 16, wp + (size_t)fi * 16);
            }
            cp_commit();
        }

        // ---- kb-split A-frag + MMA passes (keeps regs low) ----
        #pragma unroll
        for (int kb = 0; kb < 2; kb++) {
            uint32_t a[4][4];
            #pragma unroll
            for (int mf = 0; mf < 4; mf++) {
                const uint32_t base = (uint32_t)ZS_OFF(s) + kb * 2048
                                    + (uint32_t)(mf * 8 + qid) * 64;
                uint2 lo = *(const uint2*)(sm + base + sl0 * 8);
                uint2 hi = *(const uint2*)(sm + base + sl1 * 8);
                a[mf][0] = lo.x; a[mf][1] = lo.y;
                a[mf][2] = hi.x; a[mf][3] = hi.y;
            }
            #pragma unroll
            for (int nt = 0; nt < 8; nt++) {
                uint2 bv = *(const uint2*)(sm + BS_OFF(s) + b_off + nt * 512 + kb * 8);
                #pragma unroll
                for (int mf = 0; mf < 4; mf++)
                    mma_f16(acc[mf][nt], a[mf], bv.x, bv.y);
            }
        }
    }

    // ---------------- epilogue ----------------
    const float* w3s = (const float*)(sm + W3_OFF);
    float* logp = (float*)(sm + LOG_OFF);
    const int j_g = jt * 8 + qid;

    #pragma unroll
    for (int mf = 0; mf < 4; mf++) {
        #pragma unroll
        for (int half = 0; half < 2; half++) {
            const int i_g = it * 8 + mf * 2 + half;
            float* orow = out + (size_t)((b * NTOK + i_g) * NTOK + j_g) * OUTC
                        + m * 258 + wn * 64;
            float l0 = 0.f, l1 = 0.f;
            #pragma unroll
            for (int nt = 0; nt < 8; nt++) {
                float d0 = fmaxf(acc[mf][nt][half * 2],     0.f);
                float d1 = fmaxf(acc[mf][nt][half * 2 + 1], 0.f);
                int nn = nt * 8 + qpos * 2;
                float4 wv = *(const float4*)(w3s + (wn * 64 + nn) * 2);
                l0 = fmaf(d0, wv.x, fmaf(d1, wv.z, l0));
                l1 = fmaf(d0, wv.y, fmaf(d1, wv.w, l1));
                *(float2*)(orow + nn) = make_float2(d0, d1);
            }
            l0 += __shfl_xor_sync(0xffffffffu, l0, 1);
            l1 += __shfl_xor_sync(0xffffffffu, l1, 1);
            l0 += __shfl_xor_sync(0xffffffffu, l0, 2);
            l1 += __shfl_xor_sync(0xffffffffu, l1, 2);
            if (qpos == 0) {
                int r_cta = (mf * 2 + half) * 8 + qid;
                *(float2*)(logp + r_cta * 8 + wn * 2) = make_float2(l0, l1);
            }
        }
    }
    __syncthreads();

    if (tid < 64) {
        float l0 = 0.f, l1 = 0.f;
        #pragma unroll
        for (int w = 0; w < 4; w++) {
            float2 p = *(const float2*)(logp + tid * 8 + w * 2);
            l0 += p.x; l1 += p.y;
        }
        float mx = fmaxf(l0, l1);
        float e0 = __expf(l0 - mx), e1 = __expf(l1 - mx);
        float inv = 1.f / (e0 + e1);
        const int i_g = it * 8 + (tid >> 3);
        const int jg2 = jt * 8 + (tid & 7);
        float* orow = out + (size_t)((b * NTOK + i_g) * NTOK + jg2) * OUTC + m * 258;
        *(float2*)(orow + 256) = make_float2(e0 * inv, e1 * inv);
    }
}

// ---------------------------------------------------------------------------
extern "C" void kernel_launch(void* const* d_in, const int* in_sizes, int n_in,
                              void* d_out, int out_size) {
    (void)in_sizes; (void)n_in; (void)out_size;
    const float* P    = (const float*)d_in[0];
    const float* Wf1  = (const float*)d_in[1];
    const float* Wf2  = (const float*)d_in[2];
    const float* w3   = (const float*)d_in[3];
    const float* Wh1a = (const float*)d_in[4];
    const float* Wh1b = (const float*)d_in[5];
    const float* wl1  = (const float*)d_in[6];
    const float* Wh2a = (const float*)d_in[7];
    const float* Wh2b = (const float*)d_in[8];
    const float* wl2  = (const float*)d_in[9];
    float* out = (float*)d_out;

    cudaFuncSetAttribute(pair_mma,
                         cudaFuncAttributeMaxDynamicSharedMemorySize,
                         SMEM_TOTAL);

    pack_all<<<dim3(384, 1, 3), 256>>>(P, Wf1, Wh1a, Wh2a, Wf2, Wh1b, Wh2b);
    uv_mma<<<dim3(24, 8), 128, SMEM_UV>>>(out);
    pair_mma<<<dim3(16, 16, 12), 128, SMEM_TOTAL>>>(w3, wl1, wl2, out);
}

// round 15
// speedup vs baseline: 1.0986x; 1.0986x over previous
#include <cuda_runtime.h>
#include <cuda_fp16.h>
#include <cstdint>
#include <cstddef>

#define HDIM   512
#define KDIM   1024
#define DPAIR  256
#define NTOK   128
#define OUTC   774
#define NCH    32            // pair: 1024 / 32
#define NCHUV  16            // uv:   512 / 32
#define UVH_ROW 3072         // uint32 words per token row of g_UVH (6144 halves)

// device scratch (no allocs allowed)
__device__ uint32_t g_UVH[(size_t)4 * NTOK * UVH_ROW];    // u/v activations fp16 half2
__device__ uint32_t g_W2B[(size_t)3 * NCH * DPAIR * 16];  // W2 fp16 [m][c][n][qpos][kb][p]
__device__ uint32_t g_W1B[(size_t)NCHUV * 6144 * 16];     // W1 fp16 [c][n_glob][qpos][kb][p]
__device__ uint32_t g_PH [(size_t)8 * NCHUV * 1024];      // P fp16 frag chunks [blk][c][4KB]

// ---------------- pair_mma smem layout (bytes), per CTA (3 CTAs/SM) --------
#define ZS_OFF(s) ((s) * 4096)            // 2 x 4KB  -> 8192
#define BS_OFF(s) (8192 + (s) * 16384)    // 2 x 16KB -> 40960
#define W3_OFF    40960                   // 2048 -> 43008
#define UH_OFF    43008                   // 8 rows x 2080 -> 59648
#define VH_OFF    59648                   // 8 rows x 2080 -> 76288
#define LOG_OFF   0                       // overlaps ZS[0]; safe (see epilogue)
#define SMEM_TOTAL 76288                  // x3 CTAs (+3KB rsv) = 231936 <= 233472
#define UVH_STRIDE 2080                   // fp16 row stride: conflict-free uint2

// ---------------- uv_mma smem layout: 2 stages of A(4KB)+B(16KB) ----------
#define AS_UV(s)  ((s) * 20480)
#define BS_UV(s)  ((s) * 20480 + 4096)
#define SMEM_UV   40960

// ---------------- helpers ----------------
__device__ __forceinline__ uint32_t smem_u32(const void* p) {
    uint32_t a;
    asm("{ .reg .u64 t; cvta.to.shared.u64 t, %1; cvt.u32.u64 %0, t; }"
        : "=r"(a) : "l"(p));
    return a;
}
__device__ __forceinline__ void cp16(uint32_t dst, const void* src) {
    asm volatile("cp.async.cg.shared.global [%0], [%1], 16;"
                 :: "r"(dst), "l"(src));
}
__device__ __forceinline__ void cp_commit() {
    asm volatile("cp.async.commit_group;" ::: "memory");
}
__device__ __forceinline__ void cp_wait0() {
    asm volatile("cp.async.wait_group 0;" ::: "memory");
}
__device__ __forceinline__ uint32_t pack_h2(float lo, float hi) {
    __half2 hh = __halves2half2(__float2half_rn(lo), __float2half_rn(hi));
    return *reinterpret_cast<uint32_t*>(&hh);
}
// z = relu(u + v) on packed half2
__device__ __forceinline__ uint32_t hadd_relu2(uint32_t u, uint32_t v) {
    __half2 s = __hadd2(*reinterpret_cast<__half2*>(&u),
                        *reinterpret_cast<__half2*>(&v));
    __half2 z = __hmax2(s, __half2(__float2half_rn(0.f), __float2half_rn(0.f)));
    return *reinterpret_cast<uint32_t*>(&z);
}
__device__ __forceinline__ void mma_f16(float* c, const uint32_t* a,
                                        uint32_t b0, uint32_t b1) {
    asm volatile(
        "mma.sync.aligned.m16n8k16.row.col.f32.f16.f16.f32 "
        "{%0,%1,%2,%3}, {%4,%5,%6,%7}, {%8,%9}, {%0,%1,%2,%3};"
        : "+f"(c[0]), "+f"(c[1]), "+f"(c[2]), "+f"(c[3])
        : "r"(a[0]), "r"(a[1]), "r"(a[2]), "r"(a[3]), "r"(b0), "r"(b1));
}

// ---------------------------------------------------------------------------
// Kernel A: packs. z=0: W2 (96 blocks); z=1: W1 (384 blocks); z=2: P (128).
// ---------------------------------------------------------------------------
__global__ __launch_bounds__(256, 2) void pack_all(
    const float* __restrict__ P,
    const float* __restrict__ W1_0,
    const float* __restrict__ W1_1,
    const float* __restrict__ W1_2,
    const float* __restrict__ W2_0,
    const float* __restrict__ W2_1,
    const float* __restrict__ W2_2)
{
    const int bx = blockIdx.x, tid = threadIdx.x;

    if (blockIdx.z == 0) {
        if (bx >= 96) return;
        const int m = bx >> 5, c = bx & 31;
        const float* W2 = (m == 0) ? W2_0 : ((m == 1) ? W2_1 : W2_2);
        const int n = tid;
        uint32_t* dst = g_W2B + (((size_t)m * NCH + c) * DPAIR + n) * 16;
        #pragma unroll
        for (int qpos = 0; qpos < 4; qpos++)
            #pragma unroll
            for (int kb = 0; kb < 2; kb++)
                #pragma unroll
                for (int p = 0; p < 2; p++) {
                    int k = c * 32 + kb * 16 + qpos * 2 + p * 8;
                    dst[qpos * 4 + kb * 2 + p] =
                        pack_h2(W2[(size_t)k * DPAIR + n],
                                W2[(size_t)(k + 1) * DPAIR + n]);
                }
        return;
    }

    if (blockIdx.z == 1) {
        // W1 pack: B[k][n_glob] -> [c][n_glob][qpos][kb][p]; K=512.
        const int c = bx / 24, nblk = bx % 24;
        const int n = nblk * 256 + tid;
        const int m = n >> 11, half = (n >> 10) & 1, ncol = n & 1023;
        const float* W1 = (m == 0) ? W1_0 : ((m == 1) ? W1_1 : W1_2);
        const float* src = W1 + (size_t)(half * 512) * 1024 + ncol;
        uint32_t* dst = g_W1B + ((size_t)c * 6144 + n) * 16;
        #pragma unroll
        for (int qpos = 0; qpos < 4; qpos++)
            #pragma unroll
            for (int kb = 0; kb < 2; kb++)
                #pragma unroll
                for (int p = 0; p < 2; p++) {
                    int k = c * 32 + kb * 16 + qpos * 2 + p * 8;
                    dst[qpos * 4 + kb * 2 + p] =
                        pack_h2(src[(size_t)k * 1024], src[(size_t)(k + 1) * 1024]);
                }
        return;
    }

    // z == 2: P pack into Z-fragment chunk layout. 128 blocks = blk(8) x c(16).
    if (bx >= 128) return;
    {
        const int blk = bx >> 4, c = bx & 15;
        const int kb = tid >> 7, rp = (tid >> 2) & 31, e = tid & 3;
        const int hh = ((e >> 1) ^ ((rp >> 1) & 1));
        const int k = c * 32 + kb * 16 + (e & 1) * 4 + hh * 8;
        const int r0 = blk * 64 + (rp >> 3) * 16 + (rp & 7);
        float4 p0 = *(const float4*)(P + (size_t)r0 * HDIM + k);
        float4 p1 = *(const float4*)(P + (size_t)(r0 + 8) * HDIM + k);
        uint4 zo;
        zo.x = pack_h2(p0.x, p0.y);
        zo.y = pack_h2(p1.x, p1.y);
        zo.z = pack_h2(p0.z, p0.w);
        zo.w = pack_h2(p1.z, p1.w);
        uint32_t* dst = g_PH + ((size_t)(blk * NCHUV + c)) * 1024;
        *(uint4*)((char*)dst + kb * 2048 + rp * 64 + e * 16) = zo;
    }
}

// ---------------------------------------------------------------------------
// Kernel B: uv GEMM on HMMA fp16. C[512,6144] = P @ W1cat, K=512.
// Epilogue stores half2 pairs directly into g_UVH.
// ---------------------------------------------------------------------------
__global__ __launch_bounds__(128, 2) void uv_mma(float* __restrict__ dummy)
{
    extern __shared__ char sm[];
    const uint32_t sb = smem_u32(sm);
    const int tid = threadIdx.x;
    const int l = tid & 31;
    const int qid = l >> 2, qpos = l & 3;
    const int wn = tid >> 5;             // 0..3

    const int cbk = blockIdx.x;          // 24 col blocks of 256
    const int blk = blockIdx.y;          // 8 row blocks of 64
    const int cb = cbk * 256;
    const int rb = blk * 64;

    const char* Abase = (const char*)(g_PH + (size_t)blk * NCHUV * 1024);
    const char* Bbase = (const char*)(g_W1B + ((size_t)0 * 6144 + cb) * 16);

    {
        cp16(sb + AS_UV(0) + (tid * 2) * 16,     Abase + (size_t)(tid * 2) * 16);
        cp16(sb + AS_UV(0) + (tid * 2 + 1) * 16, Abase + (size_t)(tid * 2 + 1) * 16);
        #pragma unroll
        for (int q = 0; q < 8; q++) {
            int fi = q * 128 + tid;
            cp16(sb + BS_UV(0) + fi * 16, Bbase + (size_t)fi * 16);
        }
        cp_commit();
    }

    float acc[4][8][4];
    #pragma unroll
    for (int mf = 0; mf < 4; mf++)
        #pragma unroll
        for (int nt = 0; nt < 8; nt++)
            #pragma unroll
            for (int cc = 0; cc < 4; cc++) acc[mf][nt][cc] = 0.f;

    const int sl0 = qpos + 4 * ((qid >> 1) & 1);
    const int sl1 = sl0 ^ 4;
    const uint32_t b_off = (uint32_t)(wn * 64 + qid) * 64 + qpos * 16;

    for (int c = 0; c < NCHUV; c++) {
        const int s = c & 1;
        cp_wait0();
        __syncthreads();

        if (c + 1 < NCHUV) {
            const char* ap = Abase + (size_t)(c + 1) * 4096;
            const char* wp = (const char*)(g_W1B + ((size_t)(c + 1) * 6144 + cb) * 16);
            cp16(sb + AS_UV(s ^ 1) + (tid * 2) * 16,     ap + (size_t)(tid * 2) * 16);
            cp16(sb + AS_UV(s ^ 1) + (tid * 2 + 1) * 16, ap + (size_t)(tid * 2 + 1) * 16);
            #pragma unroll
            for (int q = 0; q < 8; q++) {
                int fi = q * 128 + tid;
                cp16(sb + BS_UV(s ^ 1) + fi * 16, wp + (size_t)fi * 16);
            }
            cp_commit();
        }

        uint32_t a[2][4][4];
        #pragma unroll
        for (int kb = 0; kb < 2; kb++)
            #pragma unroll
            for (int mf = 0; mf < 4; mf++) {
                const uint32_t base = (uint32_t)AS_UV(s) + kb * 2048
                                    + (uint32_t)(mf * 8 + qid) * 64;
                uint2 lo = *(const uint2*)(sm + base + sl0 * 8);
                uint2 hi = *(const uint2*)(sm + base + sl1 * 8);
                a[kb][mf][0] = lo.x; a[kb][mf][1] = lo.y;
                a[kb][mf][2] = hi.x; a[kb][mf][3] = hi.y;
            }

        #pragma unroll
        for (int nt = 0; nt < 8; nt++) {
            uint4 bv = *(const uint4*)(sm + BS_UV(s) + b_off + nt * 512);
            #pragma unroll
            for (int mf = 0; mf < 4; mf++)
                mma_f16(acc[mf][nt], a[0][mf], bv.x, bv.y);
            #pragma unroll
            for (int mf = 0; mf < 4; mf++)
                mma_f16(acc[mf][nt], a[1][mf], bv.z, bv.w);
        }
    }

    // epilogue: fp16 half2 stores to g_UVH [512][3072 u32]
    #pragma unroll
    for (int mf = 0; mf < 4; mf++) {
        #pragma unroll
        for (int half = 0; half < 2; half++) {
            const int r = rb + mf * 16 + half * 8 + qid;
            uint32_t* orow = g_UVH + (size_t)r * UVH_ROW + (cb + wn * 64) / 2;
            #pragma unroll
            for (int nt = 0; nt < 8; nt++)
                orow[nt * 4 + qpos] =
                    pack_h2(acc[mf][nt][half * 2], acc[mf][nt][half * 2 + 1]);
        }
    }
    (void)dummy;
}

// ---------------------------------------------------------------------------
// Kernel C: fp16 HMMA pair MLP. 128 threads, 4 warps, 3 CTAs/SM.
// u/v resident in SMEM as fp16 (33 KB); z = relu(u+v) via hadd2/hmax2.
// kb-split A-frag/MMA passes keep regs <= 168.
// ---------------------------------------------------------------------------
__global__ __launch_bounds__(128, 3) void pair_mma(
    const float* __restrict__ w3_0, const float* __restrict__ w3_1,
    const float* __restrict__ w3_2, float* __restrict__ out)
{
    extern __shared__ char sm[];
    const uint32_t sb = smem_u32(sm);
    const int tid = threadIdx.x;
    const int l = tid & 31;
    const int qid = l >> 2, qpos = l & 3;
    const int wn = tid >> 5;       // 0..3

    const int jt = blockIdx.x;     // 16 -> 8 j rows
    const int it = blockIdx.y;     // 16 -> 8 i rows
    const int bz = blockIdx.z;     // 12
    const int b = bz / 3, m = bz % 3;

    const float* w3 = (m == 0) ? w3_0 : ((m == 1) ? w3_1 : w3_2);
    ((float4*)(sm + W3_OFF))[tid] = ((const float4*)w3)[tid];

    const char* W2base = (const char*)(g_W2B + (size_t)m * NCH * DPAIR * 16);
    const char* Ubase = (const char*)(g_UVH + (size_t)(b * NTOK + it * 8) * UVH_ROW + m * 1024);
    const char* Vbase = (const char*)(g_UVH + (size_t)(b * NTOK + jt * 8) * UVH_ROW + m * 1024 + 512);

    // ---- prologue: resident fp16 u (8 rows x 2KB) / v (8 rows) + B chunk 0 ----
    #pragma unroll
    for (int q = 0; q < 8; q++) {              // u: 1024 x16B units
        int idx = q * 128 + tid;
        int r = idx >> 7, c16 = idx & 127;
        cp16(sb + UH_OFF + r * UVH_STRIDE + c16 * 16,
             Ubase + (size_t)r * (UVH_ROW * 4) + c16 * 16);
    }
    #pragma unroll
    for (int q = 0; q < 8; q++) {              // v: 1024 units
        int idx = q * 128 + tid;
        int r = idx >> 7, c16 = idx & 127;
        cp16(sb + VH_OFF + r * UVH_STRIDE + c16 * 16,
             Vbase + (size_t)r * (UVH_ROW * 4) + c16 * 16);
    }
    #pragma unroll
    for (int q = 0; q < 8; q++) {              // B chunk 0: 1024 units
        int fi = q * 128 + tid;
        cp16(sb + BS_OFF(0) + fi * 16, W2base + (size_t)fi * 16);
    }
    cp_commit();
    cp_wait0();
    __syncthreads();

    // ---- z-build constants (fp16 sources) ----
    const int z_rp  = tid >> 2;                 // 0..31
    const int z_e   = tid & 3;
    const int z_blk = z_rp >> 3, z_qd = z_rp & 7;
    const int z_hh  = ((z_e >> 1) ^ ((z_rp >> 1) & 1));
    const int z_kh  = (z_e & 1) * 4 + z_hh * 8;          // half index; kb adds +16
    const uint32_t z_u0 = UH_OFF + (z_blk * 2) * UVH_STRIDE + z_kh * 2;
    const uint32_t z_v  = VH_OFF + z_qd * UVH_STRIDE + z_kh * 2;
    const uint32_t z_dst = z_rp * 64 + z_e * 16;          // kb adds +2048 bytes

    float acc[4][8][4];
    #pragma unroll
    for (int mf = 0; mf < 4; mf++)
        #pragma unroll
        for (int nt = 0; nt < 8; nt++)
            #pragma unroll
            for (int cc = 0; cc < 4; cc++) acc[mf][nt][cc] = 0.f;

    // A slots: h=0/1 -> slot = qpos + 4*(h ^ ((qid>>1)&1))
    const int sl0 = qpos + 4 * ((qid >> 1) & 1);
    const int sl1 = sl0 ^ 4;
    const uint32_t b_off = (uint32_t)(wn * 64 + qid) * 64 + qpos * 16;

    for (int c = 0; c < NCH; c++) {
        const int s = c & 1;

        // ---- z-build into zs[s] (fp16 add + relu; both kb halves) ----
        {
            const uint32_t kadv = c * 64;   // c*32 halves
            #pragma unroll
            for (int kb = 0; kb < 2; kb++) {
                const uint32_t ko = kadv + kb * 32;
                uint2 u0 = *(const uint2*)(sm + z_u0 + ko);
                uint2 u1 = *(const uint2*)(sm + z_u0 + UVH_STRIDE + ko);
                uint2 vv = *(const uint2*)(sm + z_v + ko);
                uint4 zo;
                zo.x = hadd_relu2(u0.x, vv.x);
                zo.y = hadd_relu2(u1.x, vv.x);
                zo.z = hadd_relu2(u0.y, vv.y);
                zo.w = hadd_relu2(u1.y, vv.y);
                *(uint4*)(sm + ZS_OFF(s) + z_dst + kb * 2048) = zo;
            }
        }
        cp_wait0();              // B(c) arrived
        __syncthreads();         // z(c)+B(c) visible

        if (c + 1 < NCH) {       // stream B(c+1) into bs[s^1]
            const char* wp = W2base + (size_t)(c + 1) * 16384;
            #pragma unroll
            for (int q = 0; q < 8; q++) {
                int fi = q * 128 + tid;
                cp16(sb + BS_OFF(s ^ 1) + fi * 16, wp + (size_t)fi * 16);
            }
            cp_commit();
        }

        // ---- kb-split A-frag + MMA passes ----
        #pragma unroll
        for (int kb = 0; kb < 2; kb++) {
            uint32_t a[4][4];
            #pragma unroll
            for (int mf = 0; mf < 4; mf++) {
                const uint32_t base = (uint32_t)ZS_OFF(s) + kb * 2048
                                    + (uint32_t)(mf * 8 + qid) * 64;
                uint2 lo = *(const uint2*)(sm + base + sl0 * 8);
                uint2 hi = *(const uint2*)(sm + base + sl1 * 8);
                a[mf][0] = lo.x; a[mf][1] = lo.y;
                a[mf][2] = hi.x; a[mf][3] = hi.y;
            }
            #pragma unroll
            for (int nt = 0; nt < 8; nt++) {
                uint2 bv = *(const uint2*)(sm + BS_OFF(s) + b_off + nt * 512 + kb * 8);
                #pragma unroll
                for (int mf = 0; mf < 4; mf++)
                    mma_f16(acc[mf][nt], a[mf], bv.x, bv.y);
            }
        }
    }

    // ---------------- epilogue ----------------
    // LOG overlaps ZS[0]: ZS[0] last read finished before the final barrier
    // (chunk 31 uses ZS[1]); no warp reads ZS[0] after that barrier.
    const float* w3s = (const float*)(sm + W3_OFF);
    float* logp = (float*)(sm + LOG_OFF);
    const int j_g = jt * 8 + qid;

    #pragma unroll
    for (int mf = 0; mf < 4; mf++) {
        #pragma unroll
        for (int half = 0; half < 2; half++) {
            const int i_g = it * 8 + mf * 2 + half;
            float* orow = out + (size_t)((b * NTOK + i_g) * NTOK + j_g) * OUTC
                        + m * 258 + wn * 64;
            float l0 = 0.f, l1 = 0.f;
            #pragma unroll
            for (int nt = 0; nt < 8; nt++) {
                float d0 = fmaxf(acc[mf][nt][half * 2],     0.f);
                float d1 = fmaxf(acc[mf][nt][half * 2 + 1], 0.f);
                int nn = nt * 8 + qpos * 2;
                float4 wv = *(const float4*)(w3s + (wn * 64 + nn) * 2);
                l0 = fmaf(d0, wv.x, fmaf(d1, wv.z, l0));
                l1 = fmaf(d0, wv.y, fmaf(d1, wv.w, l1));
                *(float2*)(orow + nn) = make_float2(d0, d1);
            }
            l0 += __shfl_xor_sync(0xffffffffu, l0, 1);
            l1 += __shfl_xor_sync(0xffffffffu, l1, 1);
            l0 += __shfl_xor_sync(0xffffffffu, l0, 2);
            l1 += __shfl_xor_sync(0xffffffffu, l1, 2);
            if (qpos == 0) {
                int r_cta = (mf * 2 + half) * 8 + qid;
                *(float2*)(logp + r_cta * 8 + wn * 2) = make_float2(l0, l1);
            }
        }
    }
    __syncthreads();

    if (tid < 64) {
        float l0 = 0.f, l1 = 0.f;
        #pragma unroll
        for (int w = 0; w < 4; w++) {
            float2 p = *(const float2*)(logp + tid * 8 + w * 2);
            l0 += p.x; l1 += p.y;
        }
        float mx = fmaxf(l0, l1);
        float e0 = __expf(l0 - mx), e1 = __expf(l1 - mx);
        float inv = 1.f / (e0 + e1);
        const int i_g = it * 8 + (tid >> 3);
        const int jg2 = jt * 8 + (tid & 7);
        float* orow = out + (size_t)((b * NTOK + i_g) * NTOK + jg2) * OUTC + m * 258;
        *(float2*)(orow + 256) = make_float2(e0 * inv, e1 * inv);
    }
}

// ---------------------------------------------------------------------------
extern "C" void kernel_launch(void* const* d_in, const int* in_sizes, int n_in,
                              void* d_out, int out_size) {
    (void)in_sizes; (void)n_in; (void)out_size;
    const float* P    = (const float*)d_in[0];
    const float* Wf1  = (const float*)d_in[1];
    const float* Wf2  = (const float*)d_in[2];
    const float* w3   = (const float*)d_in[3];
    const float* Wh1a = (const float*)d_in[4];
    const float* Wh1b = (const float*)d_in[5];
    const float* wl1  = (const float*)d_in[6];
    const float* Wh2a = (const float*)d_in[7];
    const float* Wh2b = (const float*)d_in[8];
    const float* wl2  = (const float*)d_in[9];
    float* out = (float*)d_out;

    cudaFuncSetAttribute(pair_mma,
                         cudaFuncAttributeMaxDynamicSharedMemorySize,
                         SMEM_TOTAL);

    pack_all<<<dim3(384, 1, 3), 256>>>(P, Wf1, Wh1a, Wh2a, Wf2, Wh1b, Wh2b);
    uv_mma<<<dim3(24, 8), 128, SMEM_UV>>>(out);
    pair_mma<<<dim3(16, 16, 12), 128, SMEM_TOTAL>>>(w3, wl1, wl2, out);
}

// round 16
// speedup vs baseline: 1.1301x; 1.0287x over previous
#include <cuda_runtime.h>
#include <cuda_fp16.h>
#include <cstdint>
#include <cstddef>

#define HDIM   512
#define KDIM   1024
#define DPAIR  256
#define NTOK   128
#define OUTC   774
#define UVSTRIDE 6144
#define NCH    32            // pair: 1024 / 32
#define NCHUV  16            // uv:   512 / 32

// device scratch (no allocs allowed)
__device__ float    g_UV[(size_t)4 * NTOK * UVSTRIDE];    // u/v activations, plain k order
__device__ uint32_t g_W2B[(size_t)3 * NCH * DPAIR * 16];  // W2 fp16 [m][c][n][qpos][kb][p]
__device__ uint32_t g_W1B[(size_t)NCHUV * UVSTRIDE * 16]; // W1 fp16 [c][n_glob][qpos][kb][p]
__device__ uint32_t g_PH [(size_t)8 * NCHUV * 1024];      // P fp16 frag chunks [blk][c][4KB]

// ---------------- pair_mma smem layout (bytes), per CTA (2 CTAs/SM) --------
#define UV_STRIDE 4160                 // 1040 words/row: v-row float4 loads conflict-free
#define US_OFF    0                    // 8 rows -> 33280
#define VS_OFF    33280                // 8 rows -> 66560
#define ZS_OFF(s) (66560 + (s) * 4096)    // 2 x 4KB  -> 74752
#define BS_OFF(s) (74752 + (s) * 16384)   // 2 x 16KB -> 107520
#define W3_OFF    107520               // 2048
#define LOG_OFF   109568               // 2048
#define SMEM_TOTAL 111616              // x2 CTAs = 223232 <= 228KB

// ---------------- uv_mma smem layout: 2 stages of A(4KB)+B(16KB) ----------
#define AS_UV(s)  ((s) * 20480)
#define BS_UV(s)  ((s) * 20480 + 4096)
#define SMEM_UV   40960

// ---------------- helpers ----------------
__device__ __forceinline__ uint32_t smem_u32(const void* p) {
    uint32_t a;
    asm("{ .reg .u64 t; cvta.to.shared.u64 t, %1; cvt.u32.u64 %0, t; }"
        : "=r"(a) : "l"(p));
    return a;
}
__device__ __forceinline__ void cp16(uint32_t dst, const void* src) {
    asm volatile("cp.async.cg.shared.global [%0], [%1], 16;"
                 :: "r"(dst), "l"(src));
}
__device__ __forceinline__ void cp_commit() {
    asm volatile("cp.async.commit_group;" ::: "memory");
}
__device__ __forceinline__ void cp_wait0() {
    asm volatile("cp.async.wait_group 0;" ::: "memory");
}
__device__ __forceinline__ float2 add2(float2 a, float2 b) { // packed fp32x2 add
    float2 d;
    asm("add.rn.f32x2 %0, %1, %2;"
        : "=l"(*reinterpret_cast<unsigned long long*>(&d))
        : "l"(*reinterpret_cast<const unsigned long long*>(&a)),
          "l"(*reinterpret_cast<const unsigned long long*>(&b)));
    return d;
}
// relu + round-to-nearest fp16 pair: {lo=max(z.x,0), hi=max(z.y,0)}
__device__ __forceinline__ uint32_t cvt_relu_h2(float2 z) {
    uint32_t d;
    asm("cvt.rn.relu.f16x2.f32 %0, %1, %2;" : "=r"(d) : "f"(z.y), "f"(z.x));
    return d;
}
__device__ __forceinline__ uint32_t pack_h2(float lo, float hi) {
    __half2 hh = __halves2half2(__float2half_rn(lo), __float2half_rn(hi));
    return *reinterpret_cast<uint32_t*>(&hh);
}
__device__ __forceinline__ void mma_f16(float* c, const uint32_t* a,
                                        uint32_t b0, uint32_t b1) {
    asm volatile(
        "mma.sync.aligned.m16n8k16.row.col.f32.f16.f16.f32 "
        "{%0,%1,%2,%3}, {%4,%5,%6,%7}, {%8,%9}, {%0,%1,%2,%3};"
        : "+f"(c[0]), "+f"(c[1]), "+f"(c[2]), "+f"(c[3])
        : "r"(a[0]), "r"(a[1]), "r"(a[2]), "r"(a[3]), "r"(b0), "r"(b1));
}

// ---------------------------------------------------------------------------
// Kernel A: packs. z=0: W2 (96 blocks); z=1: W1 coalesced (384); z=2: P (128).
// ---------------------------------------------------------------------------
__global__ __launch_bounds__(256, 2) void pack_all(
    const float* __restrict__ P,
    const float* __restrict__ W1_0,
    const float* __restrict__ W1_1,
    const float* __restrict__ W1_2,
    const float* __restrict__ W2_0,
    const float* __restrict__ W2_1,
    const float* __restrict__ W2_2)
{
    const int bx = blockIdx.x, tid = threadIdx.x;

    if (blockIdx.z == 0) {
        if (bx >= 96) return;
        const int m = bx >> 5, c = bx & 31;
        const float* W2 = (m == 0) ? W2_0 : ((m == 1) ? W2_1 : W2_2);
        const int n = tid;
        uint32_t w[16];
        #pragma unroll
        for (int qpos = 0; qpos < 4; qpos++)
            #pragma unroll
            for (int kb = 0; kb < 2; kb++)
                #pragma unroll
                for (int p = 0; p < 2; p++) {
                    int k = c * 32 + kb * 16 + qpos * 2 + p * 8;
                    w[qpos * 4 + kb * 2 + p] =
                        pack_h2(W2[(size_t)k * DPAIR + n],
                                W2[(size_t)(k + 1) * DPAIR + n]);
                }
        uint4* dst = (uint4*)(g_W2B + (((size_t)m * NCH + c) * DPAIR + n) * 16);
        #pragma unroll
        for (int q = 0; q < 4; q++)
            dst[q] = *(const uint4*)(w + q * 4);
        return;
    }

    if (blockIdx.z == 1) {
        // W1 pack, coalesced: block = (c, nblk) covers 32 k x 256 n.
        // n range lies in one (m, half) since 256 | 1024.
        __shared__ float s[32][264];
        const int c = bx / 24, nblk = bx % 24;
        const int m = nblk >> 3, half = (nblk >> 2) & 1;
        const int ncol0 = (nblk & 3) * 256;
        const float* W1 = (m == 0) ? W1_0 : ((m == 1) ? W1_1 : W1_2);
        const float* rowbase = W1 + (size_t)(half * 512 + c * 32) * 1024 + ncol0;

        #pragma unroll
        for (int q = 0; q < 8; q++) {              // 2048 float4, coalesced
            int fi = q * 256 + tid;
            int kk = fi >> 6, c4 = (fi & 63) * 4;
            float4 v = *(const float4*)(rowbase + (size_t)kk * 1024 + c4);
            s[kk][c4 + 0] = v.x; s[kk][c4 + 1] = v.y;
            s[kk][c4 + 2] = v.z; s[kk][c4 + 3] = v.w;
        }
        __syncthreads();

        uint32_t w[16];
        #pragma unroll
        for (int qpos = 0; qpos < 4; qpos++)
            #pragma unroll
            for (int kb = 0; kb < 2; kb++)
                #pragma unroll
                for (int p = 0; p < 2; p++) {
                    int kl = kb * 16 + qpos * 2 + p * 8;
                    w[qpos * 4 + kb * 2 + p] = pack_h2(s[kl][tid], s[kl + 1][tid]);
                }
        const int n = nblk * 256 + tid;
        uint4* dst = (uint4*)(g_W1B + ((size_t)c * UVSTRIDE + n) * 16);
        #pragma unroll
        for (int q = 0; q < 4; q++)
            dst[q] = *(const uint4*)(w + q * 4);
        return;
    }

    // z == 2: P pack into Z-fragment chunk layout. 128 blocks = blk(8) x c(16).
    if (bx >= 128) return;
    {
        const int blk = bx >> 4, c = bx & 15;
        const int kb = tid >> 7, rp = (tid >> 2) & 31, e = tid & 3;
        const int hh = ((e >> 1) ^ ((rp >> 1) & 1));
        const int k = c * 32 + kb * 16 + (e & 1) * 4 + hh * 8;
        const int r0 = blk * 64 + (rp >> 3) * 16 + (rp & 7);
        float4 p0 = *(const float4*)(P + (size_t)r0 * HDIM + k);
        float4 p1 = *(const float4*)(P + (size_t)(r0 + 8) * HDIM + k);
        uint4 zo;
        zo.x = pack_h2(p0.x, p0.y);
        zo.y = pack_h2(p1.x, p1.y);
        zo.z = pack_h2(p0.z, p0.w);
        zo.w = pack_h2(p1.z, p1.w);
        uint32_t* dst = g_PH + ((size_t)(blk * NCHUV + c)) * 1024;
        *(uint4*)((char*)dst + kb * 2048 + rp * 64 + e * 16) = zo;
    }
}

// ---------------------------------------------------------------------------
// Kernel B: uv GEMM on HMMA fp16. C[512,6144] = P @ W1cat, K=512. (R13 keeper)
// ---------------------------------------------------------------------------
__global__ __launch_bounds__(128, 2) void uv_mma(float* __restrict__ dummy)
{
    extern __shared__ char sm[];
    const uint32_t sb = smem_u32(sm);
    const int tid = threadIdx.x;
    const int l = tid & 31;
    const int qid = l >> 2, qpos = l & 3;
    const int wn = tid >> 5;             // 0..3

    const int cbk = blockIdx.x;          // 24 col blocks of 256
    const int blk = blockIdx.y;          // 8 row blocks of 64
    const int cb = cbk * 256;
    const int rb = blk * 64;

    const char* Abase = (const char*)(g_PH + (size_t)blk * NCHUV * 1024);
    const char* Bbase = (const char*)(g_W1B + ((size_t)0 * UVSTRIDE + cb) * 16);

    {
        cp16(sb + AS_UV(0) + (tid * 2) * 16,     Abase + (size_t)(tid * 2) * 16);
        cp16(sb + AS_UV(0) + (tid * 2 + 1) * 16, Abase + (size_t)(tid * 2 + 1) * 16);
        #pragma unroll
        for (int q = 0; q < 8; q++) {
            int fi = q * 128 + tid;
            cp16(sb + BS_UV(0) + fi * 16, Bbase + (size_t)fi * 16);
        }
        cp_commit();
    }

    float acc[4][8][4];
    #pragma unroll
    for (int mf = 0; mf < 4; mf++)
        #pragma unroll
        for (int nt = 0; nt < 8; nt++)
            #pragma unroll
            for (int cc = 0; cc < 4; cc++) acc[mf][nt][cc] = 0.f;

    const int sl0 = qpos + 4 * ((qid >> 1) & 1);
    const int sl1 = sl0 ^ 4;
    const uint32_t b_off = (uint32_t)(wn * 64 + qid) * 64 + qpos * 16;

    for (int c = 0; c < NCHUV; c++) {
        const int s = c & 1;
        cp_wait0();
        __syncthreads();

        if (c + 1 < NCHUV) {
            const char* ap = Abase + (size_t)(c + 1) * 4096;
            const char* wp = (const char*)(g_W1B + ((size_t)(c + 1) * UVSTRIDE + cb) * 16);
            cp16(sb + AS_UV(s ^ 1) + (tid * 2) * 16,     ap + (size_t)(tid * 2) * 16);
            cp16(sb + AS_UV(s ^ 1) + (tid * 2 + 1) * 16, ap + (size_t)(tid * 2 + 1) * 16);
            #pragma unroll
            for (int q = 0; q < 8; q++) {
                int fi = q * 128 + tid;
                cp16(sb + BS_UV(s ^ 1) + fi * 16, wp + (size_t)fi * 16);
            }
            cp_commit();
        }

        uint32_t a[2][4][4];
        #pragma unroll
        for (int kb = 0; kb < 2; kb++)
            #pragma unroll
            for (int mf = 0; mf < 4; mf++) {
                const uint32_t base = (uint32_t)AS_UV(s) + kb * 2048
                                    + (uint32_t)(mf * 8 + qid) * 64;
                uint2 lo = *(const uint2*)(sm + base + sl0 * 8);
                uint2 hi = *(const uint2*)(sm + base + sl1 * 8);
                a[kb][mf][0] = lo.x; a[kb][mf][1] = lo.y;
                a[kb][mf][2] = hi.x; a[kb][mf][3] = hi.y;
            }

        #pragma unroll
        for (int nt = 0; nt < 8; nt++) {
            uint4 bv = *(const uint4*)(sm + BS_UV(s) + b_off + nt * 512);
            #pragma unroll
            for (int mf = 0; mf < 4; mf++)
                mma_f16(acc[mf][nt], a[0][mf], bv.x, bv.y);
            #pragma unroll
            for (int mf = 0; mf < 4; mf++)
                mma_f16(acc[mf][nt], a[1][mf], bv.z, bv.w);
        }
    }

    #pragma unroll
    for (int mf = 0; mf < 4; mf++) {
        #pragma unroll
        for (int half = 0; half < 2; half++) {
            const int r = rb + mf * 16 + half * 8 + qid;
            float* orow = g_UV + (size_t)r * UVSTRIDE + cb + wn * 64;
            #pragma unroll
            for (int nt = 0; nt < 8; nt++) {
                *(float2*)(orow + nt * 8 + qpos * 2) =
                    make_float2(acc[mf][nt][half * 2], acc[mf][nt][half * 2 + 1]);
            }
        }
    }
    (void)dummy;
}

// ---------------------------------------------------------------------------
// Kernel C: fp16 HMMA pair MLP. 128 threads, 4 warps, 2 CTAs/SM. (R13 champion)
// ---------------------------------------------------------------------------
__global__ __launch_bounds__(128, 2) void pair_mma(
    const float* __restrict__ w3_0, const float* __restrict__ w3_1,
    const float* __restrict__ w3_2, float* __restrict__ out)
{
    extern __shared__ char sm[];
    const uint32_t sb = smem_u32(sm);
    const int tid = threadIdx.x;
    const int l = tid & 31;
    const int qid = l >> 2, qpos = l & 3;
    const int wn = tid >> 5;       // 0..3

    const int jt = blockIdx.x;     // 16 -> 8 j rows
    const int it = blockIdx.y;     // 16 -> 8 i rows
    const int bz = blockIdx.z;     // 12
    const int b = bz / 3, m = bz % 3;

    const float* w3 = (m == 0) ? w3_0 : ((m == 1) ? w3_1 : w3_2);
    ((float4*)(sm + W3_OFF))[tid] = ((const float4*)w3)[tid];

    const char* W2base = (const char*)(g_W2B + (size_t)m * NCH * DPAIR * 16);
    const char* Ubase = (const char*)(g_UV + (size_t)(b * NTOK + it * 8) * UVSTRIDE + m * 2048);
    const char* Vbase = (const char*)(g_UV + (size_t)(b * NTOK + jt * 8) * UVSTRIDE + m * 2048 + 1024);

    // ---- prologue: resident u (8 rows) / v (8 rows) fp32 + B chunk 0 ----
    #pragma unroll
    for (int q = 0; q < 16; q++) {             // u: 2048 x16B units
        int idx = q * 128 + tid;
        int r = idx >> 8, c16 = idx & 255;
        cp16(sb + US_OFF + r * UV_STRIDE + c16 * 16,
             Ubase + (size_t)r * (UVSTRIDE * 4) + c16 * 16);
    }
    #pragma unroll
    for (int q = 0; q < 16; q++) {             // v: 2048 units
        int idx = q * 128 + tid;
        int r = idx >> 8, c16 = idx & 255;
        cp16(sb + VS_OFF + r * UV_STRIDE + c16 * 16,
             Vbase + (size_t)r * (UVSTRIDE * 4) + c16 * 16);
    }
    #pragma unroll
    for (int q = 0; q < 8; q++) {              // B chunk 0: 1024 units
        int fi = q * 128 + tid;
        cp16(sb + BS_OFF(0) + fi * 16, W2base + (size_t)fi * 16);
    }
    cp_commit();
    cp_wait0();
    __syncthreads();

    // ---- z-build constants (thread does kb=0 and kb=1 of its (rp,e) pair) ----
    const int z_rp  = tid >> 2;                 // 0..31
    const int z_e   = tid & 3;
    const int z_blk = z_rp >> 3, z_qd = z_rp & 7;
    const int z_hh  = ((z_e >> 1) ^ ((z_rp >> 1) & 1));
    const int z_koff = (z_e & 1) * 4 + z_hh * 8;          // kb adds +16 words
    const uint32_t z_u0 = US_OFF + (z_blk * 2) * UV_STRIDE + z_koff * 4;
    const uint32_t z_v  = VS_OFF + z_qd * UV_STRIDE + z_koff * 4;
    const uint32_t z_dst = z_rp * 64 + z_e * 16;          // kb adds +2048 bytes

    float acc[4][8][4];
    #pragma unroll
    for (int mf = 0; mf < 4; mf++)
        #pragma unroll
        for (int nt = 0; nt < 8; nt++)
            #pragma unroll
            for (int cc = 0; cc < 4; cc++) acc[mf][nt][cc] = 0.f;

    // A slots: h=0/1 -> slot = qpos + 4*(h ^ ((qid>>1)&1))
    const int sl0 = qpos + 4 * ((qid >> 1) & 1);
    const int sl1 = sl0 ^ 4;
    const uint32_t b_off = (uint32_t)(wn * 64 + qid) * 64 + qpos * 16;

    for (int c = 0; c < NCH; c++) {
        const int s = c & 1;

        // ---- cooperative z-build into zs[s] (both kb halves) ----
        {
            const uint32_t kadv = c * 128;   // c*32 floats
            #pragma unroll
            for (int kb = 0; kb < 2; kb++) {
                const uint32_t ko = kadv + kb * 64;
                float4 u0 = *(const float4*)(sm + z_u0 + ko);
                float4 u1 = *(const float4*)(sm + z_u0 + UV_STRIDE + ko);
                float4 vv = *(const float4*)(sm + z_v + ko);
                uint4 zo;
                zo.x = cvt_relu_h2(add2(make_float2(u0.x, u0.y), make_float2(vv.x, vv.y)));
                zo.y = cvt_relu_h2(add2(make_float2(u1.x, u1.y), make_float2(vv.x, vv.y)));
                zo.z = cvt_relu_h2(add2(make_float2(u0.z, u0.w), make_float2(vv.z, vv.w)));
                zo.w = cvt_relu_h2(add2(make_float2(u1.z, u1.w), make_float2(vv.z, vv.w)));
                *(uint4*)(sm + ZS_OFF(s) + z_dst + kb * 2048) = zo;
            }
        }
        cp_wait0();              // B(c) arrived
        __syncthreads();         // z(c)+B(c) visible

        if (c + 1 < NCH) {       // stream B(c+1) into bs[s^1]
            const char* wp = W2base + (size_t)(c + 1) * 16384;
            #pragma unroll
            for (int q = 0; q < 8; q++) {
                int fi = q * 128 + tid;
                cp16(sb + BS_OFF(s ^ 1) + fi * 16, wp + (size_t)fi * 16);
            }
            cp_commit();
        }

        // ---- A fragments (16 LDS.64 from zs[s]): [kb][mf][4] ----
        uint32_t a[2][4][4];
        #pragma unroll
        for (int kb = 0; kb < 2; kb++)
            #pragma unroll
            for (int mf = 0; mf < 4; mf++) {
                const uint32_t base = (uint32_t)ZS_OFF(s) + kb * 2048
                                    + (uint32_t)(mf * 8 + qid) * 64;
                uint2 lo = *(const uint2*)(sm + base + sl0 * 8);
                uint2 hi = *(const uint2*)(sm + base + sl1 * 8);
                a[kb][mf][0] = lo.x; a[kb][mf][1] = lo.y;
                a[kb][mf][2] = hi.x; a[kb][mf][3] = hi.y;
            }

        // ---- B + MMA burst: 8 LDS.128, 64 HMMA ----
        #pragma unroll
        for (int nt = 0; nt < 8; nt++) {
            uint4 bv = *(const uint4*)(sm + BS_OFF(s) + b_off + nt * 512);
            #pragma unroll
            for (int mf = 0; mf < 4; mf++)
                mma_f16(acc[mf][nt], a[0][mf], bv.x, bv.y);
            #pragma unroll
            for (int mf = 0; mf < 4; mf++)
                mma_f16(acc[mf][nt], a[1][mf], bv.z, bv.w);
        }
    }

    // ---------------- epilogue ----------------
    const float* w3s = (const float*)(sm + W3_OFF);
    float* logp = (float*)(sm + LOG_OFF);
    const int j_g = jt * 8 + qid;

    #pragma unroll
    for (int mf = 0; mf < 4; mf++) {
        #pragma unroll
        for (int half = 0; half < 2; half++) {
            const int i_g = it * 8 + mf * 2 + half;
            float* orow = out + (size_t)((b * NTOK + i_g) * NTOK + j_g) * OUTC
                        + m * 258 + wn * 64;
            float l0 = 0.f, l1 = 0.f;
            #pragma unroll
            for (int nt = 0; nt < 8; nt++) {
                float d0 = fmaxf(acc[mf][nt][half * 2],     0.f);
                float d1 = fmaxf(acc[mf][nt][half * 2 + 1], 0.f);
                int nn = nt * 8 + qpos * 2;
                float4 wv = *(const float4*)(w3s + (wn * 64 + nn) * 2);
                l0 = fmaf(d0, wv.x, fmaf(d1, wv.z, l0));
                l1 = fmaf(d0, wv.y, fmaf(d1, wv.w, l1));
                *(float2*)(orow + nn) = make_float2(d0, d1);
            }
            l0 += __shfl_xor_sync(0xffffffffu, l0, 1);
            l1 += __shfl_xor_sync(0xffffffffu, l1, 1);
            l0 += __shfl_xor_sync(0xffffffffu, l0, 2);
            l1 += __shfl_xor_sync(0xffffffffu, l1, 2);
            if (qpos == 0) {
                int r_cta = (mf * 2 + half) * 8 + qid;
                *(float2*)(logp + r_cta * 8 + wn * 2) = make_float2(l0, l1);
            }
        }
    }
    __syncthreads();

    if (tid < 64) {
        float l0 = 0.f, l1 = 0.f;
        #pragma unroll
        for (int w = 0; w < 4; w++) {
            float2 p = *(const float2*)(logp + tid * 8 + w * 2);
            l0 += p.x; l1 += p.y;
        }
        float mx = fmaxf(l0, l1);
        float e0 = __expf(l0 - mx), e1 = __expf(l1 - mx);
        float inv = 1.f / (e0 + e1);
        const int i_g = it * 8 + (tid >> 3);
        const int jg2 = jt * 8 + (tid & 7);
        float* orow = out + (size_t)((b * NTOK + i_g) * NTOK + jg2) * OUTC + m * 258;
        *(float2*)(orow + 256) = make_float2(e0 * inv, e1 * inv);
    }
}

// ---------------------------------------------------------------------------
extern "C" void kernel_launch(void* const* d_in, const int* in_sizes, int n_in,
                              void* d_out, int out_size) {
    (void)in_sizes; (void)n_in; (void)out_size;
    const float* P    = (const float*)d_in[0];
    const float* Wf1  = (const float*)d_in[1];
    const float* Wf2  = (const float*)d_in[2];
    const float* w3   = (const float*)d_in[3];
    const float* Wh1a = (const float*)d_in[4];
    const float* Wh1b = (const float*)d_in[5];
    const float* wl1  = (const float*)d_in[6];
    const float* Wh2a = (const float*)d_in[7];
    const float* Wh2b = (const float*)d_in[8];
    const float* wl2  = (const float*)d_in[9];
    float* out = (float*)d_out;

    cudaFuncSetAttribute(pair_mma,
                         cudaFuncAttributeMaxDynamicSharedMemorySize,
                         SMEM_TOTAL);

    pack_all<<<dim3(384, 1, 3), 256>>>(P, Wf1, Wh1a, Wh2a, Wf2, Wh1b, Wh2b);
    uv_mma<<<dim3(24, 8), 128, SMEM_UV>>>(out);
    pair_mma<<<dim3(16, 16, 12), 128, SMEM_TOTAL>>>(w3, wl1, wl2, out);
}

// round 17
// speedup vs baseline: 1.2098x; 1.0705x over previous
#include <cuda_runtime.h>
#include <cuda_fp16.h>
#include <cstdint>
#include <cstddef>

#define HDIM   512
#define KDIM   1024
#define DPAIR  256
#define NTOK   128
#define OUTC   774
#define UVSTRIDE 6144
#define NCH    32            // packing granularity: 1024 / 32
#define NCH2   16            // pair mainloop chunks: 1024 / 64
#define NCHUV  16            // uv: 512 / 32
#define UVH_ROW 3072         // uint32 words per token row of g_UVH (6144 halves)

// device scratch (no allocs allowed)
__device__ uint32_t g_UVH[(size_t)4 * NTOK * UVH_ROW];    // u/v activations fp16 half2
__device__ uint32_t g_W2B[(size_t)3 * NCH * DPAIR * 16];  // W2 fp16 [m][c][n][qpos][kb][p]
__device__ uint32_t g_W1B[(size_t)NCHUV * UVSTRIDE * 16]; // W1 fp16 [c][n_glob][qpos][kb][p]
__device__ uint32_t g_PH [(size_t)8 * NCHUV * 1024];      // P fp16 frag chunks [blk][c][4KB]

// ---------------- pair_mma smem (bytes), per CTA (2 CTAs/SM), KC=64 --------
#define UVH_STRIDE 2080                   // fp16 row stride: conflict-free uint2
#define UH_OFF    0                       // 8 rows x 2080 -> 16640
#define VH_OFF    16640                   // 8 rows -> 33280
#define ZS_OFF(s) (33280 + (s) * 8192)    // 2 x 8KB (two 4KB subs) -> 49664
#define BS_OFF(s) (49664 + (s) * 32768)   // 2 x 32KB -> 115200
#define LOG_OFF   33280                   // overlaps ZS[0]; safe (last chunk uses ZS[1])
#define SMEM_TOTAL 115200                 // x2 CTAs = 230400 <= 233472

// ---------------- uv_mma smem layout: 2 stages of A(4KB)+B(16KB) ----------
#define AS_UV(s)  ((s) * 20480)
#define BS_UV(s)  ((s) * 20480 + 4096)
#define SMEM_UV   40960

// ---------------- helpers ----------------
__device__ __forceinline__ uint32_t smem_u32(const void* p) {
    uint32_t a;
    asm("{ .reg .u64 t; cvta.to.shared.u64 t, %1; cvt.u32.u64 %0, t; }"
        : "=r"(a) : "l"(p));
    return a;
}
__device__ __forceinline__ void cp16(uint32_t dst, const void* src) {
    asm volatile("cp.async.cg.shared.global [%0], [%1], 16;"
                 :: "r"(dst), "l"(src));
}
__device__ __forceinline__ void cp_commit() {
    asm volatile("cp.async.commit_group;" ::: "memory");
}
__device__ __forceinline__ void cp_wait0() {
    asm volatile("cp.async.wait_group 0;" ::: "memory");
}
__device__ __forceinline__ uint32_t pack_h2(float lo, float hi) {
    __half2 hh = __halves2half2(__float2half_rn(lo), __float2half_rn(hi));
    return *reinterpret_cast<uint32_t*>(&hh);
}
// z = relu(u + v) on packed half2
__device__ __forceinline__ uint32_t hadd_relu2(uint32_t u, uint32_t v) {
    __half2 s = __hadd2(*reinterpret_cast<__half2*>(&u),
                        *reinterpret_cast<__half2*>(&v));
    __half2 z = __hmax2(s, __half2(__float2half_rn(0.f), __float2half_rn(0.f)));
    return *reinterpret_cast<uint32_t*>(&z);
}
__device__ __forceinline__ void mma_f16(float* c, const uint32_t* a,
                                        uint32_t b0, uint32_t b1) {
    asm volatile(
        "mma.sync.aligned.m16n8k16.row.col.f32.f16.f16.f32 "
        "{%0,%1,%2,%3}, {%4,%5,%6,%7}, {%8,%9}, {%0,%1,%2,%3};"
        : "+f"(c[0]), "+f"(c[1]), "+f"(c[2]), "+f"(c[3])
        : "r"(a[0]), "r"(a[1]), "r"(a[2]), "r"(a[3]), "r"(b0), "r"(b1));
}

// ---------------------------------------------------------------------------
// Kernel A: packs. z=0: W2 (96 blocks); z=1: W1 coalesced (384); z=2: P (128).
// ---------------------------------------------------------------------------
__global__ __launch_bounds__(256, 2) void pack_all(
    const float* __restrict__ P,
    const float* __restrict__ W1_0,
    const float* __restrict__ W1_1,
    const float* __restrict__ W1_2,
    const float* __restrict__ W2_0,
    const float* __restrict__ W2_1,
    const float* __restrict__ W2_2)
{
    const int bx = blockIdx.x, tid = threadIdx.x;

    if (blockIdx.z == 0) {
        if (bx >= 96) return;
        const int m = bx >> 5, c = bx & 31;
        const float* W2 = (m == 0) ? W2_0 : ((m == 1) ? W2_1 : W2_2);
        const int n = tid;
        uint32_t w[16];
        #pragma unroll
        for (int qpos = 0; qpos < 4; qpos++)
            #pragma unroll
            for (int kb = 0; kb < 2; kb++)
                #pragma unroll
                for (int p = 0; p < 2; p++) {
                    int k = c * 32 + kb * 16 + qpos * 2 + p * 8;
                    w[qpos * 4 + kb * 2 + p] =
                        pack_h2(W2[(size_t)k * DPAIR + n],
                                W2[(size_t)(k + 1) * DPAIR + n]);
                }
        uint4* dst = (uint4*)(g_W2B + (((size_t)m * NCH + c) * DPAIR + n) * 16);
        #pragma unroll
        for (int q = 0; q < 4; q++)
            dst[q] = *(const uint4*)(w + q * 4);
        return;
    }

    if (blockIdx.z == 1) {
        // W1 pack, coalesced: block = (c, nblk) covers 32 k x 256 n.
        __shared__ float s[32][264];
        const int c = bx / 24, nblk = bx % 24;
        const int m = nblk >> 3, half = (nblk >> 2) & 1;
        const int ncol0 = (nblk & 3) * 256;
        const float* W1 = (m == 0) ? W1_0 : ((m == 1) ? W1_1 : W1_2);
        const float* rowbase = W1 + (size_t)(half * 512 + c * 32) * 1024 + ncol0;

        #pragma unroll
        for (int q = 0; q < 8; q++) {              // 2048 float4, coalesced
            int fi = q * 256 + tid;
            int kk = fi >> 6, c4 = (fi & 63) * 4;
            float4 v = *(const float4*)(rowbase + (size_t)kk * 1024 + c4);
            s[kk][c4 + 0] = v.x; s[kk][c4 + 1] = v.y;
            s[kk][c4 + 2] = v.z; s[kk][c4 + 3] = v.w;
        }
        __syncthreads();

        uint32_t w[16];
        #pragma unroll
        for (int qpos = 0; qpos < 4; qpos++)
            #pragma unroll
            for (int kb = 0; kb < 2; kb++)
                #pragma unroll
                for (int p = 0; p < 2; p++) {
                    int kl = kb * 16 + qpos * 2 + p * 8;
                    w[qpos * 4 + kb * 2 + p] = pack_h2(s[kl][tid], s[kl + 1][tid]);
                }
        const int n = nblk * 256 + tid;
        uint4* dst = (uint4*)(g_W1B + ((size_t)c * UVSTRIDE + n) * 16);
        #pragma unroll
        for (int q = 0; q < 4; q++)
            dst[q] = *(const uint4*)(w + q * 4);
        return;
    }

    // z == 2: P pack into Z-fragment chunk layout. 128 blocks = blk(8) x c(16).
    if (bx >= 128) return;
    {
        const int blk = bx >> 4, c = bx & 15;
        const int kb = tid >> 7, rp = (tid >> 2) & 31, e = tid & 3;
        const int hh = ((e >> 1) ^ ((rp >> 1) & 1));
        const int k = c * 32 + kb * 16 + (e & 1) * 4 + hh * 8;
        const int r0 = blk * 64 + (rp >> 3) * 16 + (rp & 7);
        float4 p0 = *(const float4*)(P + (size_t)r0 * HDIM + k);
        float4 p1 = *(const float4*)(P + (size_t)(r0 + 8) * HDIM + k);
        uint4 zo;
        zo.x = pack_h2(p0.x, p0.y);
        zo.y = pack_h2(p1.x, p1.y);
        zo.z = pack_h2(p0.z, p0.w);
        zo.w = pack_h2(p1.z, p1.w);
        uint32_t* dst = g_PH + ((size_t)(blk * NCHUV + c)) * 1024;
        *(uint4*)((char*)dst + kb * 2048 + rp * 64 + e * 16) = zo;
    }
}

// ---------------------------------------------------------------------------
// Kernel B: uv GEMM on HMMA fp16. C[512,6144] = P @ W1cat, K=512.
// Epilogue stores half2 pairs directly into g_UVH.
// ---------------------------------------------------------------------------
__global__ __launch_bounds__(128, 2) void uv_mma(float* __restrict__ dummy)
{
    extern __shared__ char sm[];
    const uint32_t sb = smem_u32(sm);
    const int tid = threadIdx.x;
    const int l = tid & 31;
    const int qid = l >> 2, qpos = l & 3;
    const int wn = tid >> 5;             // 0..3

    const int cbk = blockIdx.x;          // 24 col blocks of 256
    const int blk = blockIdx.y;          // 8 row blocks of 64
    const int cb = cbk * 256;
    const int rb = blk * 64;

    const char* Abase = (const char*)(g_PH + (size_t)blk * NCHUV * 1024);
    const char* Bbase = (const char*)(g_W1B + ((size_t)0 * UVSTRIDE + cb) * 16);

    {
        cp16(sb + AS_UV(0) + (tid * 2) * 16,     Abase + (size_t)(tid * 2) * 16);
        cp16(sb + AS_UV(0) + (tid * 2 + 1) * 16, Abase + (size_t)(tid * 2 + 1) * 16);
        #pragma unroll
        for (int q = 0; q < 8; q++) {
            int fi = q * 128 + tid;
            cp16(sb + BS_UV(0) + fi * 16, Bbase + (size_t)fi * 16);
        }
        cp_commit();
    }

    float acc[4][8][4];
    #pragma unroll
    for (int mf = 0; mf < 4; mf++)
        #pragma unroll
        for (int nt = 0; nt < 8; nt++)
            #pragma unroll
            for (int cc = 0; cc < 4; cc++) acc[mf][nt][cc] = 0.f;

    const int sl0 = qpos + 4 * ((qid >> 1) & 1);
    const int sl1 = sl0 ^ 4;
    const uint32_t b_off = (uint32_t)(wn * 64 + qid) * 64 + qpos * 16;

    for (int c = 0; c < NCHUV; c++) {
        const int s = c & 1;
        cp_wait0();
        __syncthreads();

        if (c + 1 < NCHUV) {
            const char* ap = Abase + (size_t)(c + 1) * 4096;
            const char* wp = (const char*)(g_W1B + ((size_t)(c + 1) * UVSTRIDE + cb) * 16);
            cp16(sb + AS_UV(s ^ 1) + (tid * 2) * 16,     ap + (size_t)(tid * 2) * 16);
            cp16(sb + AS_UV(s ^ 1) + (tid * 2 + 1) * 16, ap + (size_t)(tid * 2 + 1) * 16);
            #pragma unroll
            for (int q = 0; q < 8; q++) {
                int fi = q * 128 + tid;
                cp16(sb + BS_UV(s ^ 1) + fi * 16, wp + (size_t)fi * 16);
            }
            cp_commit();
        }

        uint32_t a[2][4][4];
        #pragma unroll
        for (int kb = 0; kb < 2; kb++)
            #pragma unroll
            for (int mf = 0; mf < 4; mf++) {
                const uint32_t base = (uint32_t)AS_UV(s) + kb * 2048
                                    + (uint32_t)(mf * 8 + qid) * 64;
                uint2 lo = *(const uint2*)(sm + base + sl0 * 8);
                uint2 hi = *(const uint2*)(sm + base + sl1 * 8);
                a[kb][mf][0] = lo.x; a[kb][mf][1] = lo.y;
                a[kb][mf][2] = hi.x; a[kb][mf][3] = hi.y;
            }

        #pragma unroll
        for (int nt = 0; nt < 8; nt++) {
            uint4 bv = *(const uint4*)(sm + BS_UV(s) + b_off + nt * 512);
            #pragma unroll
            for (int mf = 0; mf < 4; mf++)
                mma_f16(acc[mf][nt], a[0][mf], bv.x, bv.y);
            #pragma unroll
            for (int mf = 0; mf < 4; mf++)
                mma_f16(acc[mf][nt], a[1][mf], bv.z, bv.w);
        }
    }

    // epilogue: fp16 half2 stores to g_UVH [512][3072 u32]
    #pragma unroll
    for (int mf = 0; mf < 4; mf++) {
        #pragma unroll
        for (int half = 0; half < 2; half++) {
            const int r = rb + mf * 16 + half * 8 + qid;
            uint32_t* orow = g_UVH + (size_t)r * UVH_ROW + (cb + wn * 64) / 2;
            #pragma unroll
            for (int nt = 0; nt < 8; nt++)
                orow[nt * 4 + qpos] =
                    pack_h2(acc[mf][nt][half * 2], acc[mf][nt][half * 2 + 1]);
        }
    }
    (void)dummy;
}

// ---------------------------------------------------------------------------
// Kernel C: fp16 HMMA pair MLP, KC=64 (16 chunks). 128 threads, 2 CTAs/SM.
// u/v resident fp16 (33 KB); B double-buffered 2x32KB; one barrier per chunk.
// ---------------------------------------------------------------------------
__global__ __launch_bounds__(128, 2) void pair_mma(
    const float* __restrict__ w3_0, const float* __restrict__ w3_1,
    const float* __restrict__ w3_2, float* __restrict__ out)
{
    extern __shared__ char sm[];
    const uint32_t sb = smem_u32(sm);
    const int tid = threadIdx.x;
    const int l = tid & 31;
    const int qid = l >> 2, qpos = l & 3;
    const int wn = tid >> 5;       // 0..3

    const int jt = blockIdx.x;     // 16 -> 8 j rows
    const int it = blockIdx.y;     // 16 -> 8 i rows
    const int bz = blockIdx.z;     // 12
    const int b = bz / 3, m = bz % 3;

    const float* w3 = (m == 0) ? w3_0 : ((m == 1) ? w3_1 : w3_2);

    const char* W2base = (const char*)(g_W2B + (size_t)m * NCH * DPAIR * 16);
    const char* Ubase = (const char*)(g_UVH + (size_t)(b * NTOK + it * 8) * UVH_ROW + m * 1024);
    const char* Vbase = (const char*)(g_UVH + (size_t)(b * NTOK + jt * 8) * UVH_ROW + m * 1024 + 512);

    // ---- prologue: resident fp16 u/v (8 rows x 2KB each) + B chunk 0 (32KB) ----
    #pragma unroll
    for (int q = 0; q < 8; q++) {              // u: 1024 x16B units
        int idx = q * 128 + tid;
        int r = idx >> 7, c16 = idx & 127;
        cp16(sb + UH_OFF + r * UVH_STRIDE + c16 * 16,
             Ubase + (size_t)r * (UVH_ROW * 4) + c16 * 16);
    }
    #pragma unroll
    for (int q = 0; q < 8; q++) {              // v: 1024 units
        int idx = q * 128 + tid;
        int r = idx >> 7, c16 = idx & 127;
        cp16(sb + VH_OFF + r * UVH_STRIDE + c16 * 16,
             Vbase + (size_t)r * (UVH_ROW * 4) + c16 * 16);
    }
    #pragma unroll
    for (int q = 0; q < 16; q++) {             // B chunk 0: 2048 units
        int fi = q * 128 + tid;
        cp16(sb + BS_OFF(0) + fi * 16, W2base + (size_t)fi * 16);
    }
    cp_commit();
    cp_wait0();
    __syncthreads();

    // ---- z-build constants (fp16 sources) ----
    const int z_rp  = tid >> 2;                 // 0..31
    const int z_e   = tid & 3;
    const int z_blk = z_rp >> 3, z_qd = z_rp & 7;
    const int z_hh  = ((z_e >> 1) ^ ((z_rp >> 1) & 1));
    const int z_kh  = (z_e & 1) * 4 + z_hh * 8;          // half idx within 32-k sub
    const uint32_t z_u0 = UH_OFF + (z_blk * 2) * UVH_STRIDE + z_kh * 2;
    const uint32_t z_v  = VH_OFF + z_qd * UVH_STRIDE + z_kh * 2;
    const uint32_t z_dst = z_rp * 64 + z_e * 16;          // kb +2048, sub +4096

    float acc[4][8][4];
    #pragma unroll
    for (int mf = 0; mf < 4; mf++)
        #pragma unroll
        for (int nt = 0; nt < 8; nt++)
            #pragma unroll
            for (int cc = 0; cc < 4; cc++) acc[mf][nt][cc] = 0.f;

    // A slots: h=0/1 -> slot = qpos + 4*(h ^ ((qid>>1)&1))
    const int sl0 = qpos + 4 * ((qid >> 1) & 1);
    const int sl1 = sl0 ^ 4;
    const uint32_t b_off = (uint32_t)(wn * 64 + qid) * 64 + qpos * 16;

    for (int c = 0; c < NCH2; c++) {
        const int s = c & 1;

        // ---- z-build into zs[s]: two 32-k subs x two kb halves ----
        #pragma unroll
        for (int sub = 0; sub < 2; sub++) {
            const uint32_t kadv = (uint32_t)(c * 2 + sub) * 64;   // bytes (32 halves)
            #pragma unroll
            for (int kb = 0; kb < 2; kb++) {
                const uint32_t ko = kadv + kb * 32;
                uint2 u0 = *(const uint2*)(sm + z_u0 + ko);
                uint2 u1 = *(const uint2*)(sm + z_u0 + UVH_STRIDE + ko);
                uint2 vv = *(const uint2*)(sm + z_v + ko);
                uint4 zo;
                zo.x = hadd_relu2(u0.x, vv.x);
                zo.y = hadd_relu2(u1.x, vv.x);
                zo.z = hadd_relu2(u0.y, vv.y);
                zo.w = hadd_relu2(u1.y, vv.y);
                *(uint4*)(sm + ZS_OFF(s) + sub * 4096 + z_dst + kb * 2048) = zo;
            }
        }
        cp_wait0();              // B(c) arrived
        __syncthreads();         // z(c)+B(c) visible

        if (c + 1 < NCH2) {      // stream B(c+1) (32KB) into bs[s^1]
            const char* wp = W2base + (size_t)(c + 1) * 32768;
            #pragma unroll
            for (int q = 0; q < 16; q++) {
                int fi = q * 128 + tid;
                cp16(sb + BS_OFF(s ^ 1) + fi * 16, wp + (size_t)fi * 16);
            }
            cp_commit();
        }

        // ---- two sub-passes: A-frags + 64-HMMA burst each ----
        #pragma unroll
        for (int sub = 0; sub < 2; sub++) {
            uint32_t a[2][4][4];
            #pragma unroll
            for (int kb = 0; kb < 2; kb++)
                #pragma unroll
                for (int mf = 0; mf < 4; mf++) {
                    const uint32_t base = (uint32_t)ZS_OFF(s) + sub * 4096
                                        + kb * 2048 + (uint32_t)(mf * 8 + qid) * 64;
                    uint2 lo = *(const uint2*)(sm + base + sl0 * 8);
                    uint2 hi = *(const uint2*)(sm + base + sl1 * 8);
                    a[kb][mf][0] = lo.x; a[kb][mf][1] = lo.y;
                    a[kb][mf][2] = hi.x; a[kb][mf][3] = hi.y;
                }
            #pragma unroll
            for (int nt = 0; nt < 8; nt++) {
                uint4 bv = *(const uint4*)(sm + BS_OFF(s) + sub * 16384
                                           + b_off + nt * 512);
                #pragma unroll
                for (int mf = 0; mf < 4; mf++)
                    mma_f16(acc[mf][nt], a[0][mf], bv.x, bv.y);
                #pragma unroll
                for (int mf = 0; mf < 4; mf++)
                    mma_f16(acc[mf][nt], a[1][mf], bv.z, bv.w);
            }
        }
    }

    // ---------------- epilogue ----------------
    // LOG overlaps ZS[0]; last chunk (c=15) used ZS[1], so ZS[0] has no readers.
    float* logp = (float*)(sm + LOG_OFF);
    const int j_g = jt * 8 + qid;

    #pragma unroll
    for (int mf = 0; mf < 4; mf++) {
        #pragma unroll
        for (int half = 0; half < 2; half++) {
            const int i_g = it * 8 + mf * 2 + half;
            float* orow = out + (size_t)((b * NTOK + i_g) * NTOK + j_g) * OUTC
                        + m * 258 + wn * 64;
            float l0 = 0.f, l1 = 0.f;
            #pragma unroll
            for (int nt = 0; nt < 8; nt++) {
                float d0 = fmaxf(acc[mf][nt][half * 2],     0.f);
                float d1 = fmaxf(acc[mf][nt][half * 2 + 1], 0.f);
                int nn = nt * 8 + qpos * 2;
                float4 wv = *(const float4*)(w3 + (wn * 64 + nn) * 2);
                l0 = fmaf(d0, wv.x, fmaf(d1, wv.z, l0));
                l1 = fmaf(d0, wv.y, fmaf(d1, wv.w, l1));
                *(float2*)(orow + nn) = make_float2(d0, d1);
            }
            l0 += __shfl_xor_sync(0xffffffffu, l0, 1);
            l1 += __shfl_xor_sync(0xffffffffu, l1, 1);
            l0 += __shfl_xor_sync(0xffffffffu, l0, 2);
            l1 += __shfl_xor_sync(0xffffffffu, l1, 2);
            if (qpos == 0) {
                int r_cta = (mf * 2 + half) * 8 + qid;
                *(float2*)(logp + r_cta * 8 + wn * 2) = make_float2(l0, l1);
            }
        }
    }
    __syncthreads();

    if (tid < 64) {
        float l0 = 0.f, l1 = 0.f;
        #pragma unroll
        for (int w = 0; w < 4; w++) {
            float2 p = *(const float2*)(logp + tid * 8 + w * 2);
            l0 += p.x; l1 += p.y;
        }
        float mx = fmaxf(l0, l1);
        float e0 = __expf(l0 - mx), e1 = __expf(l1 - mx);
        float inv = 1.f / (e0 + e1);
        const int i_g = it * 8 + (tid >> 3);
        const int jg2 = jt * 8 + (tid & 7);
        float* orow = out + (size_t)((b * NTOK + i_g) * NTOK + jg2) * OUTC + m * 258;
        *(float2*)(orow + 256) = make_float2(e0 * inv, e1 * inv);
    }
}

// ---------------------------------------------------------------------------
extern "C" void kernel_launch(void* const* d_in, const int* in_sizes, int n_in,
                              void* d_out, int out_size) {
    (void)in_sizes; (void)n_in; (void)out_size;
    const float* P    = (const float*)d_in[0];
    const float* Wf1  = (const float*)d_in[1];
    const float* Wf2  = (const float*)d_in[2];
    const float* w3   = (const float*)d_in[3];
    const float* Wh1a = (const float*)d_in[4];
    const float* Wh1b = (const float*)d_in[5];
    const float* wl1  = (const float*)d_in[6];
    const float* Wh2a = (const float*)d_in[7];
    const float* Wh2b = (const float*)d_in[8];
    const float* wl2  = (const float*)d_in[9];
    float* out = (float*)d_out;

    cudaFuncSetAttribute(pair_mma,
                         cudaFuncAttributeMaxDynamicSharedMemorySize,
                         SMEM_TOTAL);

    pack_all<<<dim3(384, 1, 3), 256>>>(P, Wf1, Wh1a, Wh2a, Wf2, Wh1b, Wh2b);
    uv_mma<<<dim3(24, 8), 128, SMEM_UV>>>(out);
    pair_mma<<<dim3(16, 16, 12), 128, SMEM_TOTAL>>>(w3, wl1, wl2, out);
}